// round 16
// baseline (speedup 1.0000x reference)
#include <cuda_runtime.h>
#include <cuda_bf16.h>
#include <cstdint>

typedef uint32_t u32;
typedef uint64_t u64;

#define D_  256
#define H1_ 512
#define H2_ 256
#define E_  16
#define EG_ 8           // experts per CTA group
#define O_  64
#define B_  32768
#define MT  32          // batch rows per CTA
#define NT  256         // threads (8 warps: 1m x 8n; each warp owns both m-frags)

// ---------- fragment-packed weight buffers ----------
// layout: [e][kt][nt][lane(32)][w4] u32 where w4 = {h.w0, h.w1, l.w0, l.w1}
__device__ u32 g_w1p[16u * 16 * 64 * 32 * 4];   // 2,097,152 u32
__device__ u32 g_w2p[16u * 32 * 32 * 32 * 4];   // 2,097,152 u32
__device__ float g_v[16 * 256];                  // v_e = W3[e] @ head_w
__device__ float g_c[16];                        // c_e = b3[e] . head_w
__device__ float g_part[2 * B_];                 // per-expert-group partial sums

// per-expert byte strides (tile bytes)
#define W1_EB 524288u   // 16kt * 64nt * 512B
#define W2_EB 524288u   // 32kt * 32nt * 512B

// ---------- SMEM (bytes), per CTA (two CTAs co-resident) ----------
#define SM_XH    0        // x hi frags  [16kt][2mt][32][16B] = 16384
#define SM_XL    16384
#define SM_H1H   32768    // h1 hi frags [32kt][2mt][...] = 32768
#define SM_H1L   65536
#define SM_GATES 98304    // [32][16] f32 = 2048
#define SM_YACC  100352   // [32] f32
#define SMEM_BYTES 100480

__device__ __forceinline__ void mma_bf16(float* d, const uint4& a, u32 b0, u32 b1) {
    asm volatile(
        "mma.sync.aligned.m16n8k16.row.col.f32.bf16.bf16.f32 "
        "{%0,%1,%2,%3}, {%4,%5,%6,%7}, {%8,%9}, {%0,%1,%2,%3};"
        : "+f"(d[0]), "+f"(d[1]), "+f"(d[2]), "+f"(d[3])
        : "r"(a.x), "r"(a.y), "r"(a.z), "r"(a.w), "r"(b0), "r"(b1));
}

__device__ __forceinline__ void split2(float a, float b, u32& hi, u32& lo) {
    __nv_bfloat16 ha = __float2bfloat16(a), hb = __float2bfloat16(b);
    float ra = a - __bfloat162float(ha), rb = b - __bfloat162float(hb);
    __nv_bfloat16 la = __float2bfloat16(ra), lb = __float2bfloat16(rb);
    hi = (u32)__bfloat16_as_ushort(ha) | ((u32)__bfloat16_as_ushort(hb) << 16);
    lo = (u32)__bfloat16_as_ushort(la) | ((u32)__bfloat16_as_ushort(lb) << 16);
}

// ---------------- weight converter: W1/W2 frags + v_e/c_e (verified) ---------
__global__ void convert_weights_kernel(const float* __restrict__ W1,
                                       const float* __restrict__ W2,
                                       const float* __restrict__ W3,
                                       const float* __restrict__ b3,
                                       const float* __restrict__ head_w) {
    const u32 N1 = 16u * 16 * 64 * 32 * 4;
    const u32 N2 = 16u * 32 * 32 * 32 * 4;
    u32 i = blockIdx.x * blockDim.x + threadIdx.x;

    if (i >= N1 + N2) {
        u32 j = i - (N1 + N2);
        if (j < 16u * 256) {               // v[e][k] = sum_o W3[e][k][o] * head_w[o]
            u32 e = j >> 8, k = j & 255;
            const float* wp = W3 + ((size_t)e * 256 + k) * 64;
            float s = 0.f;
            #pragma unroll 8
            for (int o = 0; o < 64; o++) s = fmaf(wp[o], head_w[o], s);
            g_v[j] = s;
        } else if (j < 16u * 256 + 16) {   // c[e] = b3[e] . head_w
            u32 e = j - 16u * 256;
            const float* bp = b3 + (size_t)e * 64;
            float s = 0.f;
            #pragma unroll 8
            for (int o = 0; o < 64; o++) s = fmaf(bp[o], head_w[o], s);
            g_c[e] = s;
        }
        return;
    }

    const float* src; u32* dst; u32 idx, K, Nn;
    if (i < N1) { src = W1; dst = g_w1p; idx = i;      K = 256; Nn = 512; }
    else        { src = W2; dst = g_w2p; idx = i - N1; K = 512; Nn = 256; }

    u32 w4 = idx & 3;                // {h.w0, h.w1, l.w0, l.w1}
    u32 word = w4 & 1, part = w4 >> 1;
    u32 lane = (idx >> 2) & 31;
    u32 rest = idx >> 7;             // [e][kt][nt]
    u32 ntc = Nn / 8;
    u32 nt = rest % ntc; rest /= ntc;
    u32 ktc = K / 16;
    u32 kt = rest % ktc; u32 e = rest / ktc;

    u32 n  = nt * 8 + (lane >> 2);
    u32 k0 = kt * 16 + (lane & 3) * 2 + word * 8;
    float v0 = src[((size_t)e * K + k0)     * Nn + n];
    float v1 = src[((size_t)e * K + k0 + 1) * Nn + n];
    u32 hi, lo;
    split2(v0, v1, hi, lo);
    dst[idx] = part ? lo : hi;
}

// ---------------- finalize: out = part0 + part1 + head_b ----------------
__global__ void finalize_kernel(const float* __restrict__ head_b,
                                float* __restrict__ out) {
    int i = blockIdx.x * blockDim.x + threadIdx.x;
    if (i < B_)
        out[i] = g_part[i] + g_part[B_ + i] + head_b[0];
}

template<int NJ>
__device__ __forceinline__ void load_B(uint4* B, const char* bk, int l) {
    #pragma unroll
    for (int j = 0; j < NJ; j++)
        B[j] = *(const uint4*)(bk + j * 512 + l * 16);
}

// A frags: A[0]=hi m0, A[1]=hi m1, A[2]=lo m0, A[3]=lo m1
__device__ __forceinline__ void load_A(uint4* A, const char* smem, int base_h, int base_l,
                                       int kt, int l) {
    A[0] = *(const uint4*)(smem + base_h + (kt * 2)     * 512 + l * 16);
    A[1] = *(const uint4*)(smem + base_h + (kt * 2 + 1) * 512 + l * 16);
    A[2] = *(const uint4*)(smem + base_l + (kt * 2)     * 512 + l * 16);
    A[3] = *(const uint4*)(smem + base_l + (kt * 2 + 1) * 512 + l * 16);
}

// term-grouped MMAs over 2 m-frags x NJ cols; B[j] = {Bh0,Bh1,Bl0,Bl1}
template<int NJ>
__device__ __forceinline__ void mma_terms(float acc[][NJ][4], const uint4* A, const uint4* B) {
    #pragma unroll
    for (int m = 0; m < 2; m++)
        #pragma unroll
        for (int j = 0; j < NJ; j++) mma_bf16(acc[m][j], A[m], B[j].x, B[j].y);
    #pragma unroll
    for (int m = 0; m < 2; m++)
        #pragma unroll
        for (int j = 0; j < NJ; j++) mma_bf16(acc[m][j], A[m], B[j].z, B[j].w);
    #pragma unroll
    for (int m = 0; m < 2; m++)
        #pragma unroll
        for (int j = 0; j < NJ; j++) mma_bf16(acc[m][j], A[2 + m], B[j].x, B[j].y);
}

// ---------------- main fused kernel (one expert-group of 8 per CTA) ---------
__global__ __launch_bounds__(NT, 2)
void moe_yts_mma_kernel(const float* __restrict__ x,
                        const float* __restrict__ gate_w,
                        const float* __restrict__ gate_b,
                        const float* __restrict__ b1,
                        const float* __restrict__ b2)
{
    extern __shared__ char smem[];
    const int t  = threadIdx.x;
    const int wn = t >> 5, l = t & 31;        // warp grid 1(m) x 8(n)
    const int g  = l >> 2, q = l & 3;
    const int b_base = blockIdx.x * MT;
    const int eg = blockIdx.y;                // expert group 0/1
    const int e0 = eg * EG_;

    float* gates = (float*)(smem + SM_GATES);
    float* yacc  = (float*)(smem + SM_YACC);

    // ---- gate logits: row r = t>>3 (0..31), experts (t&7)*2..+1 ----
    {
        int r = t >> 3, ee0 = (t & 7) * 2;
        float a0 = gate_b[ee0], a1 = gate_b[ee0 + 1];
        const float* xr = x + (size_t)(b_base + r) * D_;
        for (int d = 0; d < D_; d++) {
            float xv = xr[d];
            float2 gw = *(const float2*)(gate_w + d * E_ + ee0);
            a0 = fmaf(xv, gw.x, a0); a1 = fmaf(xv, gw.y, a1);
        }
        gates[r * E_ + ee0] = a0; gates[r * E_ + ee0 + 1] = a1;
    }

    // ---- x -> A-fragments (hi/lo): 32 rows x 256 cols ----
    for (int idx = t; idx < MT * (D_ / 4); idx += NT) {
        int r = idx >> 6, c4 = idx & 63;
        float4 v = *(const float4*)(x + (size_t)(b_base + r) * D_ + c4 * 4);
        int kt = c4 >> 2, kk = (c4 & 3) * 4;
        int mtr = r >> 4, rr = r & 15, gg = rr & 7;
        int lane0 = gg * 4 + ((kk & 7) >> 1);
        int wsel = (kk >= 8 ? 2 : 0) + (rr >= 8 ? 1 : 0);
        u32 h0, l0, h1w, l1w;
        split2(v.x, v.y, h0, l0);
        split2(v.z, v.w, h1w, l1w);
        u32 off = (u32)((kt * 2 + mtr) * 512 + lane0 * 16 + wsel * 4);
        *(u32*)(smem + SM_XH + off)      = h0;
        *(u32*)(smem + SM_XH + off + 16) = h1w;
        *(u32*)(smem + SM_XL + off)      = l0;
        *(u32*)(smem + SM_XL + off + 16) = l1w;
    }
    __syncthreads();

    // ---- softmax rows (all 16 experts; this CTA uses its 8) + zero yacc ----
    if (t < MT) {
        float* row = gates + t * E_;
        float m = row[0];
        #pragma unroll
        for (int j = 1; j < E_; j++) m = fmaxf(m, row[j]);
        float s = 0.f;
        #pragma unroll
        for (int j = 0; j < E_; j++) { float v = expf(row[j] - m); row[j] = v; s += v; }
        float inv = 1.0f / s;
        #pragma unroll
        for (int j = 0; j < E_; j++) row[j] *= inv;
        yacc[t] = 0.f;
    }
    __syncthreads();

    for (int e = e0; e < e0 + EG_; e++) {
        // ==== GEMM1: [32,256]@[256,512]; warp: 32 rows x 64 cols, 2 subpasses ====
        #pragma unroll 1
        for (int sub = 0; sub < 2; sub++) {
            float acc[2][4][4];
            #pragma unroll
            for (int m = 0; m < 2; m++)
                #pragma unroll
                for (int j = 0; j < 4; j++)
                    #pragma unroll
                    for (int c = 0; c < 4; c++) acc[m][j][c] = 0.f;

            const char* wb = (const char*)g_w1p + (size_t)e * W1_EB
                           + (size_t)(wn * 8 + sub * 4) * 512;
            uint4 Bb[2][4], Ab[2][4];
            load_B<4>(Bb[0], wb, l);
            load_A(Ab[0], smem, SM_XH, SM_XL, 0, l);
            #pragma unroll 2
            for (int kt = 0; kt < 16; kt++) {
                if (kt < 15) {
                    load_B<4>(Bb[(kt + 1) & 1], wb + (size_t)(kt + 1) * 32768, l);
                    load_A(Ab[(kt + 1) & 1], smem, SM_XH, SM_XL, kt + 1, l);
                }
                mma_terms<4>(acc, Ab[kt & 1], Bb[kt & 1]);
            }
            int bn = wn * 64 + sub * 32;
            #pragma unroll
            for (int m = 0; m < 2; m++) {
                #pragma unroll
                for (int jj = 0; jj < 2; jj++) {
                    const float* bp = b1 + e * H1_ + bn + jj * 16;
                    float b00 = bp[q * 2], b01 = bp[q * 2 + 1];
                    float b10 = bp[8 + q * 2], b11 = bp[9 + q * 2];
                    float r00 = fmaxf(acc[m][2*jj][0]   + b00, 0.f), r01 = fmaxf(acc[m][2*jj][1]   + b01, 0.f);
                    float r02 = fmaxf(acc[m][2*jj][2]   + b00, 0.f), r03 = fmaxf(acc[m][2*jj][3]   + b01, 0.f);
                    float r10 = fmaxf(acc[m][2*jj+1][0] + b10, 0.f), r11 = fmaxf(acc[m][2*jj+1][1] + b11, 0.f);
                    float r12 = fmaxf(acc[m][2*jj+1][2] + b10, 0.f), r13 = fmaxf(acc[m][2*jj+1][3] + b11, 0.f);
                    uint4 H, L;
                    split2(r00, r01, H.x, L.x);
                    split2(r02, r03, H.y, L.y);
                    split2(r10, r11, H.z, L.z);
                    split2(r12, r13, H.w, L.w);
                    int ktp = wn * 4 + sub * 2 + jj;
                    *(uint4*)(smem + SM_H1H + (ktp * 2 + m) * 512 + l * 16) = H;
                    *(uint4*)(smem + SM_H1L + (ktp * 2 + m) * 512 + l * 16) = L;
                }
            }
        }
        __syncthreads();

        // ==== GEMM2 + fused GEMM3/head: [32,512]@[512,256]; warp 32 cols ====
        {
            float acc[2][4][4];
            #pragma unroll
            for (int m = 0; m < 2; m++)
                #pragma unroll
                for (int j = 0; j < 4; j++)
                    #pragma unroll
                    for (int c = 0; c < 4; c++) acc[m][j][c] = 0.f;

            const char* wb = (const char*)g_w2p + (size_t)e * W2_EB + (size_t)(wn * 4) * 512;
            uint4 Bb[2][4], Ab[2][4];
            load_B<4>(Bb[0], wb, l);
            load_A(Ab[0], smem, SM_H1H, SM_H1L, 0, l);
            #pragma unroll 2
            for (int kt = 0; kt < 32; kt++) {
                if (kt < 31) {
                    load_B<4>(Bb[(kt + 1) & 1], wb + (size_t)(kt + 1) * 16384, l);
                    load_A(Ab[(kt + 1) & 1], smem, SM_H1H, SM_H1L, kt + 1, l);
                }
                mma_terms<4>(acc, Ab[kt & 1], Bb[kt & 1]);
            }
            // fused epilogue: y-partial = relu(h2 + b2) . v_e, gated; rows g,g+8,16+g,24+g
            const float* ve = g_v + e * 256;
            const float* bp = b2 + e * H2_;
            float py[4] = {0.f, 0.f, 0.f, 0.f};
            #pragma unroll
            for (int j = 0; j < 4; j++) {
                int c0 = wn * 32 + j * 8 + q * 2;
                float b20 = bp[c0], b21 = bp[c0 + 1];
                float v0 = ve[c0], v1 = ve[c0 + 1];
                #pragma unroll
                for (int m = 0; m < 2; m++) {
                    py[m*2]   += fmaxf(acc[m][j][0] + b20, 0.f) * v0 + fmaxf(acc[m][j][1] + b21, 0.f) * v1;
                    py[m*2+1] += fmaxf(acc[m][j][2] + b20, 0.f) * v0 + fmaxf(acc[m][j][3] + b21, 0.f) * v1;
                }
            }
            #pragma unroll
            for (int m = 0; m < 2; m++) {
                int r0 = m * 16 + g, r1 = r0 + 8;
                py[m*2]   *= gates[r0 * E_ + e];
                py[m*2+1] *= gates[r1 * E_ + e];
            }
            #pragma unroll
            for (int k = 0; k < 4; k++) {
                py[k] += __shfl_xor_sync(0xffffffffu, py[k], 1);
                py[k] += __shfl_xor_sync(0xffffffffu, py[k], 2);
            }
            if (q == 0) {
                atomicAdd(&yacc[g],      py[0]);
                atomicAdd(&yacc[g + 8],  py[1]);
                atomicAdd(&yacc[g + 16], py[2]);
                atomicAdd(&yacc[g + 24], py[3]);
            }
        }
        __syncthreads();   // h1 reads done; yacc consistent; next expert may overwrite h1
    }

    if (t < MT) {
        float s = yacc[t];
        const float* gr = gates + t * E_;
        #pragma unroll
        for (int e = 0; e < EG_; e++) s = fmaf(gr[e0 + e], g_c[e0 + e], s);
        g_part[eg * B_ + b_base + t] = s;
    }
}

extern "C" void kernel_launch(void* const* d_in, const int* in_sizes, int n_in,
                              void* d_out, int out_size) {
    const float* x      = (const float*)d_in[0];
    const float* gate_w = (const float*)d_in[1];
    const float* gate_b = (const float*)d_in[2];
    const float* W1     = (const float*)d_in[3];
    const float* b1     = (const float*)d_in[4];
    const float* W2     = (const float*)d_in[5];
    const float* b2     = (const float*)d_in[6];
    const float* W3     = (const float*)d_in[7];
    const float* b3     = (const float*)d_in[8];
    const float* head_w = (const float*)d_in[9];
    const float* head_b = (const float*)d_in[10];
    float* out = (float*)d_out;

    const u32 total_words = 16u*16*64*32*4 + 16u*32*32*32*4 + 16u*256 + 16u;
    convert_weights_kernel<<<(total_words + 255) / 256, 256>>>(W1, W2, W3, b3, head_w);

    cudaFuncSetAttribute(moe_yts_mma_kernel,
                         cudaFuncAttributeMaxDynamicSharedMemorySize, SMEM_BYTES);
    moe_yts_mma_kernel<<<dim3(B_ / MT, 2), NT, SMEM_BYTES>>>(
        x, gate_w, gate_b, b1, b2);

    finalize_kernel<<<B_ / 256, 256>>>(head_b, out);
}

// round 17
// speedup vs baseline: 1.0353x; 1.0353x over previous
#include <cuda_runtime.h>
#include <cuda_bf16.h>
#include <cstdint>

typedef uint32_t u32;
typedef uint64_t u64;

#define D_  256
#define H1_ 512
#define H2_ 256
#define E_  16
#define O_  64
#define B_  32768
#define MT  32          // batch rows per CTA
#define NT  256         // threads (8 warps: 1m x 8n; each warp owns both m-frags)

// ---------- fragment-packed weight buffers ----------
// layout: [e][kt][nt][lane(32)][w4] u32 where w4 = {h.w0, h.w1, l.w0, l.w1}
__device__ u32 g_w1p[16u * 16 * 64 * 32 * 4];   // 2,097,152 u32
__device__ u32 g_w2p[16u * 32 * 32 * 32 * 4];   // 2,097,152 u32
__device__ float g_v[16 * 256];                  // v_e = W3[e] @ head_w
__device__ float g_c[16];                        // c_e = b3[e] . head_w

// per-expert byte strides (tile bytes)
#define W1_EB 524288u   // 16kt * 64nt * 512B
#define W2_EB 524288u   // 32kt * 32nt * 512B

// ---------- SMEM (bytes), per CTA (two CTAs co-resident) ----------
#define SM_XH    0        // x hi frags  [16kt][2mt][32][16B] = 16384
#define SM_XL    16384
#define SM_H1H   32768    // h1 hi frags [32kt][2mt][...] = 32768
#define SM_H1L   65536
#define SM_GATES 98304    // [32][16] f32 = 2048
#define SM_YACC  100352   // [32] f32
#define SMEM_BYTES 100480

__device__ __forceinline__ void mma_bf16(float* d, const uint4& a, u32 b0, u32 b1) {
    asm volatile(
        "mma.sync.aligned.m16n8k16.row.col.f32.bf16.bf16.f32 "
        "{%0,%1,%2,%3}, {%4,%5,%6,%7}, {%8,%9}, {%0,%1,%2,%3};"
        : "+f"(d[0]), "+f"(d[1]), "+f"(d[2]), "+f"(d[3])
        : "r"(a.x), "r"(a.y), "r"(a.z), "r"(a.w), "r"(b0), "r"(b1));
}

__device__ __forceinline__ void split2(float a, float b, u32& hi, u32& lo) {
    __nv_bfloat16 ha = __float2bfloat16(a), hb = __float2bfloat16(b);
    float ra = a - __bfloat162float(ha), rb = b - __bfloat162float(hb);
    __nv_bfloat16 la = __float2bfloat16(ra), lb = __float2bfloat16(rb);
    hi = (u32)__bfloat16_as_ushort(ha) | ((u32)__bfloat16_as_ushort(hb) << 16);
    lo = (u32)__bfloat16_as_ushort(la) | ((u32)__bfloat16_as_ushort(lb) << 16);
}

// ---------------- weight converter: compile-time shapes (shift-only math) ----
template<int K, int Nn>
__device__ __forceinline__ void conv_frag(const float* __restrict__ src,
                                          u32* __restrict__ dst, u32 idx) {
    // idx layout: [e][kt][nt][lane][w4]
    u32 w4 = idx & 3;                // {h.w0, h.w1, l.w0, l.w1}
    u32 word = w4 & 1, part = w4 >> 1;
    u32 lane = (idx >> 2) & 31;
    u32 rest = idx >> 7;             // [e][kt][nt]
    constexpr u32 NTC = Nn / 8;      // power of two
    constexpr u32 KTC = K / 16;      // power of two
    u32 nt = rest & (NTC - 1); rest /= NTC;
    u32 kt = rest & (KTC - 1);
    u32 e  = rest / KTC;

    u32 n  = nt * 8 + (lane >> 2);
    u32 k0 = kt * 16 + (lane & 3) * 2 + word * 8;
    float v0 = src[((size_t)e * K + k0)     * Nn + n];
    float v1 = src[((size_t)e * K + k0 + 1) * Nn + n];
    u32 hi, lo;
    split2(v0, v1, hi, lo);
    dst[idx] = part ? lo : hi;
}

__global__ void convert_weights_kernel(const float* __restrict__ W1,
                                       const float* __restrict__ W2,
                                       const float* __restrict__ W3,
                                       const float* __restrict__ b3,
                                       const float* __restrict__ head_w) {
    const u32 N1 = 16u * 16 * 64 * 32 * 4;
    const u32 N2 = 16u * 32 * 32 * 32 * 4;
    u32 i = blockIdx.x * blockDim.x + threadIdx.x;

    if (i < N1) {
        conv_frag<256, 512>(W1, g_w1p, i);
    } else if (i < N1 + N2) {
        conv_frag<512, 256>(W2, g_w2p, i - N1);
    } else {
        u32 j = i - (N1 + N2);
        if (j < 16u * 256) {               // v[e][k] = sum_o W3[e][k][o] * head_w[o]
            const float* wp = W3 + (size_t)j * 64;
            float s = 0.f;
            #pragma unroll 8
            for (int o = 0; o < 64; o++) s = fmaf(wp[o], head_w[o], s);
            g_v[j] = s;
        } else if (j < 16u * 256 + 16) {   // c[e] = b3[e] . head_w
            u32 e = j - 16u * 256;
            const float* bp = b3 + (size_t)e * 64;
            float s = 0.f;
            #pragma unroll 8
            for (int o = 0; o < 64; o++) s = fmaf(bp[o], head_w[o], s);
            g_c[e] = s;
        }
    }
}

template<int NJ>
__device__ __forceinline__ void load_B(uint4* B, const char* bk, int l) {
    #pragma unroll
    for (int j = 0; j < NJ; j++)
        B[j] = *(const uint4*)(bk + j * 512 + l * 16);
}

// A frags: A[0]=hi m0, A[1]=hi m1, A[2]=lo m0, A[3]=lo m1
__device__ __forceinline__ void load_A(uint4* A, const char* smem, int base_h, int base_l,
                                       int kt, int l) {
    A[0] = *(const uint4*)(smem + base_h + (kt * 2)     * 512 + l * 16);
    A[1] = *(const uint4*)(smem + base_h + (kt * 2 + 1) * 512 + l * 16);
    A[2] = *(const uint4*)(smem + base_l + (kt * 2)     * 512 + l * 16);
    A[3] = *(const uint4*)(smem + base_l + (kt * 2 + 1) * 512 + l * 16);
}

// term-grouped MMAs over 2 m-frags x NJ cols; B[j] = {Bh0,Bh1,Bl0,Bl1}
template<int NJ>
__device__ __forceinline__ void mma_terms(float acc[][NJ][4], const uint4* A, const uint4* B) {
    #pragma unroll
    for (int m = 0; m < 2; m++)
        #pragma unroll
        for (int j = 0; j < NJ; j++) mma_bf16(acc[m][j], A[m], B[j].x, B[j].y);
    #pragma unroll
    for (int m = 0; m < 2; m++)
        #pragma unroll
        for (int j = 0; j < NJ; j++) mma_bf16(acc[m][j], A[m], B[j].z, B[j].w);
    #pragma unroll
    for (int m = 0; m < 2; m++)
        #pragma unroll
        for (int j = 0; j < NJ; j++) mma_bf16(acc[m][j], A[2 + m], B[j].x, B[j].y);
}

// One GEMM phase: assumes Bb[0] already holds this phase's kt0 fragments.
// During the last kt, prefetches `nxt` (next phase's kt0) into Bb[0].
template<int NKT, u32 STRIDE>
__device__ __forceinline__ void run_phase(float acc[2][4][4], const char* smem,
                                          int base_h, int base_l,
                                          const char* wb, const char* nxt,
                                          int l, uint4 Bb[2][4], uint4 Ab[2][4]) {
    static_assert((NKT & 1) == 0, "NKT even: last kt consumes Bb[1], freeing Bb[0]");
    load_A(Ab[0], smem, base_h, base_l, 0, l);
    #pragma unroll 2
    for (int kt = 0; kt < NKT; kt++) {
        if (kt < NKT - 1) {
            load_B<4>(Bb[(kt + 1) & 1], wb + (size_t)(kt + 1) * STRIDE, l);
            load_A(Ab[(kt + 1) & 1], smem, base_h, base_l, kt + 1, l);
        } else {
            load_B<4>(Bb[0], nxt, l);   // cross-barrier prefetch of next phase
        }
        mma_terms<4>(acc, Ab[kt & 1], Bb[kt & 1]);
    }
}

// ---------------- main fused kernel ----------------
__global__ __launch_bounds__(NT, 2)
void moe_yts_mma_kernel(const float* __restrict__ x,
                        const float* __restrict__ gate_w,
                        const float* __restrict__ gate_b,
                        const float* __restrict__ b1,
                        const float* __restrict__ b2,
                        const float* __restrict__ head_b,
                        float* __restrict__ out)
{
    extern __shared__ char smem[];
    const int t  = threadIdx.x;
    const int wn = t >> 5, l = t & 31;        // warp grid 1(m) x 8(n)
    const int g  = l >> 2, q = l & 3;
    const int b_base = blockIdx.x * MT;

    float* gates = (float*)(smem + SM_GATES);
    float* yacc  = (float*)(smem + SM_YACC);

    // ---- gate logits: row r = t>>3 (0..31), experts (t&7)*2..+1 ----
    {
        int r = t >> 3, e0 = (t & 7) * 2;
        float a0 = gate_b[e0], a1 = gate_b[e0 + 1];
        const float* xr = x + (size_t)(b_base + r) * D_;
        for (int d = 0; d < D_; d++) {
            float xv = xr[d];
            float2 gw = *(const float2*)(gate_w + d * E_ + e0);
            a0 = fmaf(xv, gw.x, a0); a1 = fmaf(xv, gw.y, a1);
        }
        gates[r * E_ + e0] = a0; gates[r * E_ + e0 + 1] = a1;
    }

    // ---- x -> A-fragments (hi/lo): 32 rows x 256 cols ----
    for (int idx = t; idx < MT * (D_ / 4); idx += NT) {
        int r = idx >> 6, c4 = idx & 63;
        float4 v = *(const float4*)(x + (size_t)(b_base + r) * D_ + c4 * 4);
        int kt = c4 >> 2, kk = (c4 & 3) * 4;
        int mtr = r >> 4, rr = r & 15, gg = rr & 7;
        int lane0 = gg * 4 + ((kk & 7) >> 1);
        int wsel = (kk >= 8 ? 2 : 0) + (rr >= 8 ? 1 : 0);
        u32 h0, l0, h1w, l1w;
        split2(v.x, v.y, h0, l0);
        split2(v.z, v.w, h1w, l1w);
        u32 off = (u32)((kt * 2 + mtr) * 512 + lane0 * 16 + wsel * 4);
        *(u32*)(smem + SM_XH + off)      = h0;
        *(u32*)(smem + SM_XH + off + 16) = h1w;
        *(u32*)(smem + SM_XL + off)      = l0;
        *(u32*)(smem + SM_XL + off + 16) = l1w;
    }
    __syncthreads();

    // ---- softmax rows + zero yacc ----
    if (t < MT) {
        float* row = gates + t * E_;
        float m = row[0];
        #pragma unroll
        for (int j = 1; j < E_; j++) m = fmaxf(m, row[j]);
        float s = 0.f;
        #pragma unroll
        for (int j = 0; j < E_; j++) { float v = expf(row[j] - m); row[j] = v; s += v; }
        float inv = 1.0f / s;
        #pragma unroll
        for (int j = 0; j < E_; j++) row[j] *= inv;
        yacc[t] = 0.f;
    }
    __syncthreads();

    uint4 Bb[2][4], Ab[2][4];
    // preload first phase's kt0 B-fragments (expert 0, GEMM1 sub 0)
    load_B<4>(Bb[0], (const char*)g_w1p + (size_t)(wn * 8) * 512, l);

    for (int e = 0; e < E_; e++) {
        const char* w1e = (const char*)g_w1p + (size_t)e * W1_EB;
        const char* w2e = (const char*)g_w2p + (size_t)e * W2_EB;
        const char* w1n = (const char*)g_w1p + (size_t)(e + 1 < E_ ? e + 1 : e) * W1_EB;

        // ==== GEMM1: [32,256]@[256,512]; warp: 32 rows x 64 cols, 2 subpasses ====
        #pragma unroll 1
        for (int sub = 0; sub < 2; sub++) {
            float acc[2][4][4];
            #pragma unroll
            for (int m = 0; m < 2; m++)
                #pragma unroll
                for (int j = 0; j < 4; j++)
                    #pragma unroll
                    for (int c = 0; c < 4; c++) acc[m][j][c] = 0.f;

            const char* wb  = w1e + (size_t)(wn * 8 + sub * 4) * 512;
            const char* nxt = (sub == 0) ? w1e + (size_t)(wn * 8 + 4) * 512
                                         : w2e + (size_t)(wn * 4) * 512;
            run_phase<16, 32768u>(acc, smem, SM_XH, SM_XL, wb, nxt, l, Bb, Ab);

            int bn = wn * 64 + sub * 32;
            #pragma unroll
            for (int m = 0; m < 2; m++) {
                #pragma unroll
                for (int jj = 0; jj < 2; jj++) {
                    const float* bp = b1 + e * H1_ + bn + jj * 16;
                    float b00 = bp[q * 2], b01 = bp[q * 2 + 1];
                    float b10 = bp[8 + q * 2], b11 = bp[9 + q * 2];
                    float r00 = fmaxf(acc[m][2*jj][0]   + b00, 0.f), r01 = fmaxf(acc[m][2*jj][1]   + b01, 0.f);
                    float r02 = fmaxf(acc[m][2*jj][2]   + b00, 0.f), r03 = fmaxf(acc[m][2*jj][3]   + b01, 0.f);
                    float r10 = fmaxf(acc[m][2*jj+1][0] + b10, 0.f), r11 = fmaxf(acc[m][2*jj+1][1] + b11, 0.f);
                    float r12 = fmaxf(acc[m][2*jj+1][2] + b10, 0.f), r13 = fmaxf(acc[m][2*jj+1][3] + b11, 0.f);
                    uint4 H, L;
                    split2(r00, r01, H.x, L.x);
                    split2(r02, r03, H.y, L.y);
                    split2(r10, r11, H.z, L.z);
                    split2(r12, r13, H.w, L.w);
                    int ktp = wn * 4 + sub * 2 + jj;
                    *(uint4*)(smem + SM_H1H + (ktp * 2 + m) * 512 + l * 16) = H;
                    *(uint4*)(smem + SM_H1L + (ktp * 2 + m) * 512 + l * 16) = L;
                }
            }
        }
        __syncthreads();

        // ==== GEMM2 + fused GEMM3/head: [32,512]@[512,256]; warp 32 cols ====
        {
            float acc[2][4][4];
            #pragma unroll
            for (int m = 0; m < 2; m++)
                #pragma unroll
                for (int j = 0; j < 4; j++)
                    #pragma unroll
                    for (int c = 0; c < 4; c++) acc[m][j][c] = 0.f;

            const char* wb  = w2e + (size_t)(wn * 4) * 512;
            const char* nxt = w1n + (size_t)(wn * 8) * 512;
            run_phase<32, 16384u>(acc, smem, SM_H1H, SM_H1L, wb, nxt, l, Bb, Ab);

            // fused epilogue: y-partial = relu(h2 + b2) . v_e, gated; rows g,g+8,16+g,24+g
            const float* ve = g_v + e * 256;
            const float* bp = b2 + e * H2_;
            float py[4] = {0.f, 0.f, 0.f, 0.f};
            #pragma unroll
            for (int j = 0; j < 4; j++) {
                int c0 = wn * 32 + j * 8 + q * 2;
                float b20 = bp[c0], b21 = bp[c0 + 1];
                float v0 = ve[c0], v1 = ve[c0 + 1];
                #pragma unroll
                for (int m = 0; m < 2; m++) {
                    py[m*2]   += fmaxf(acc[m][j][0] + b20, 0.f) * v0 + fmaxf(acc[m][j][1] + b21, 0.f) * v1;
                    py[m*2+1] += fmaxf(acc[m][j][2] + b20, 0.f) * v0 + fmaxf(acc[m][j][3] + b21, 0.f) * v1;
                }
            }
            #pragma unroll
            for (int m = 0; m < 2; m++) {
                int r0 = m * 16 + g, r1 = r0 + 8;
                py[m*2]   *= gates[r0 * E_ + e];
                py[m*2+1] *= gates[r1 * E_ + e];
            }
            #pragma unroll
            for (int k = 0; k < 4; k++) {
                py[k] += __shfl_xor_sync(0xffffffffu, py[k], 1);
                py[k] += __shfl_xor_sync(0xffffffffu, py[k], 2);
            }
            if (q == 0) {
                atomicAdd(&yacc[g],      py[0]);
                atomicAdd(&yacc[g + 8],  py[1]);
                atomicAdd(&yacc[g + 16], py[2]);
                atomicAdd(&yacc[g + 24], py[3]);
            }
        }
        __syncthreads();   // h1 reads done; yacc consistent; next expert may overwrite h1
    }

    if (t < MT) {
        float s = yacc[t] + head_b[0];
        const float* gr = gates + t * E_;
        #pragma unroll
        for (int e = 0; e < E_; e++) s = fmaf(gr[e], g_c[e], s);
        out[b_base + t] = s;
    }
}

extern "C" void kernel_launch(void* const* d_in, const int* in_sizes, int n_in,
                              void* d_out, int out_size) {
    const float* x      = (const float*)d_in[0];
    const float* gate_w = (const float*)d_in[1];
    const float* gate_b = (const float*)d_in[2];
    const float* W1     = (const float*)d_in[3];
    const float* b1     = (const float*)d_in[4];
    const float* W2     = (const float*)d_in[5];
    const float* b2     = (const float*)d_in[6];
    const float* W3     = (const float*)d_in[7];
    const float* b3     = (const float*)d_in[8];
    const float* head_w = (const float*)d_in[9];
    const float* head_b = (const float*)d_in[10];
    float* out = (float*)d_out;

    const u32 total_words = 16u*16*64*32*4 + 16u*32*32*32*4 + 16u*256 + 16u;
    convert_weights_kernel<<<(total_words + 255) / 256, 256>>>(W1, W2, W3, b3, head_w);

    cudaFuncSetAttribute(moe_yts_mma_kernel,
                         cudaFuncAttributeMaxDynamicSharedMemorySize, SMEM_BYTES);
    moe_yts_mma_kernel<<<B_ / MT, NT, SMEM_BYTES>>>(
        x, gate_w, gate_b, b1, b2, head_b, out);
}